// round 2
// baseline (speedup 1.0000x reference)
#include <cuda_runtime.h>
#include <cstdint>

// Embedding gather: out[token, :] = weight[idx[token], :]
// idx: [8192] int32, weight: [32000, 512] f32, out: [8192, 512] f32
//
// One CTA per token row. 128 threads/CTA, each thread moves one float4
// (16 B) of the 2 KB row. Fully coalesced 128-bit LDG/STG.

static constexpr int DIM = 512;          // floats per row
static constexpr int VEC_PER_ROW = DIM / 4;  // 128 float4 per row

__global__ void __launch_bounds__(128, 16)
embedding_gather_kernel(const int* __restrict__ idx,
                        const float4* __restrict__ weight,
                        float4* __restrict__ out,
                        int n_tokens)
{
    const int token = blockIdx.x;
    if (token >= n_tokens) return;

    const int row = __ldg(&idx[token]);

    const float4* src = weight + (long long)row * VEC_PER_ROW;
    float4* dst = out + (long long)token * VEC_PER_ROW;

    // 128 threads, 128 float4 per row: one vector each.
    dst[threadIdx.x] = __ldg(&src[threadIdx.x]);
}

extern "C" void kernel_launch(void* const* d_in, const int* in_sizes, int n_in,
                              void* d_out, int out_size)
{
    const int*   idx    = (const int*)d_in[0];        // x: [4, 2048] int32
    const float* weight = (const float*)d_in[1];      // [32000, 512] f32
    float*       out    = (float*)d_out;              // [4, 2048, 512] f32

    const int n_tokens = in_sizes[0];                 // 8192

    embedding_gather_kernel<<<n_tokens, 128>>>(
        idx, (const float4*)weight, (float4*)out, n_tokens);
}

// round 3
// speedup vs baseline: 1.2620x; 1.2620x over previous
#include <cuda_runtime.h>
#include <cstdint>

// Embedding gather: out[token, :] = weight[idx[token], :]
// idx: [8192] int32, weight: [32000, 512] f32, out: [8192, 512] f32
//
// Latency-optimized: each CTA (256 thr) moves 16 token rows (32 KB).
// Indices staged in smem, then 8 independent LDG.128 per thread
// (MLP=8) before any store.

static constexpr int VEC_PER_ROW   = 128;  // 512 f32 = 128 float4
static constexpr int TOKENS_PER_CTA = 16;
static constexpr int THREADS        = 256;
static constexpr int VEC_PER_CTA    = TOKENS_PER_CTA * VEC_PER_ROW; // 2048
static constexpr int UNROLL         = VEC_PER_CTA / THREADS;        // 8

__global__ void __launch_bounds__(THREADS, 8)
embedding_gather_kernel(const int* __restrict__ idx,
                        const float4* __restrict__ weight,
                        float4* __restrict__ out)
{
    __shared__ int s_idx[TOKENS_PER_CTA];

    const int tid        = threadIdx.x;
    const int base_token = blockIdx.x * TOKENS_PER_CTA;

    if (tid < TOKENS_PER_CTA)
        s_idx[tid] = __ldg(&idx[base_token + tid]);
    __syncthreads();

    float4 v[UNROLL];

    // Front-batched independent loads: MLP = 8 per thread.
#pragma unroll
    for (int k = 0; k < UNROLL; k++) {
        const int j = tid + k * THREADS;      // 0..2047 within CTA
        const int t = j >> 7;                 // token within CTA
        const int c = j & (VEC_PER_ROW - 1);  // vec within row
        v[k] = __ldg(&weight[(long long)s_idx[t] * VEC_PER_ROW + c]);
    }

#pragma unroll
    for (int k = 0; k < UNROLL; k++) {
        const int j = tid + k * THREADS;
        const int t = j >> 7;
        const int c = j & (VEC_PER_ROW - 1);
        out[(long long)(base_token + t) * VEC_PER_ROW + c] = v[k];
    }
}

extern "C" void kernel_launch(void* const* d_in, const int* in_sizes, int n_in,
                              void* d_out, int out_size)
{
    const int*   idx    = (const int*)d_in[0];    // x: [4, 2048] int32
    const float* weight = (const float*)d_in[1];  // [32000, 512] f32
    float*       out    = (float*)d_out;          // [4, 2048, 512] f32

    const int n_tokens = in_sizes[0];             // 8192
    const int n_ctas   = n_tokens / TOKENS_PER_CTA; // 512

    embedding_gather_kernel<<<n_ctas, THREADS>>>(
        idx, (const float4*)weight, (float4*)out);
}